// round 14
// baseline (speedup 1.0000x reference)
#include <cuda_runtime.h>
#include <cuda_fp16.h>
#include <math.h>
#include <stdint.h>

#define B_  4
#define S_  2048
#define H_  1024
#define NH  16
#define M_  (B_ * S_)          // 8192 rows

// ------------------------- scratch (__device__ globals) --------------------
__device__ float g_U[(size_t)M_ * H_];                 // 32 MB : U (fp32, biased)
__device__ float g_attn[(size_t)M_ * H_];              // 32 MB
__device__ __half g_xh[(size_t)M_ * H_];
__device__ __half g_gh[(size_t)M_ * H_];
__device__ __half g_Wp16[(size_t)H_ * 4 * H_];         // Wp [1024,4096] fp16 (K,N)
__device__ __half g_Wt16[(size_t)H_ * H_];             // Wt [1024,1024] fp16 (K,N)
__device__ float g_rope[2048 * 32 * 2];                // cos,sin table
// attention operands in [b*h][s][64] layout
__device__ __half g_qh[(size_t)M_ * H_];
__device__ __half g_kh[(size_t)M_ * H_];
__device__ __half g_vh[(size_t)M_ * H_];

// ------------------------- helpers -----------------------------------------
__device__ __forceinline__ uint32_t smem_u32(const void* p) {
    uint32_t a;
    asm("{ .reg .u64 t; cvta.to.shared.u64 t, %1; cvt.u32.u64 %0, t; }"
        : "=r"(a) : "l"(p));
    return a;
}

#define SWZ(r, c) ((uint32_t)((r) * 64 + (((c) ^ (((r) >> 1) & 3)) * 16)))

#define CP_ASYNC16(dst, src) \
    asm volatile("cp.async.cg.shared.global [%0], [%1], 16;" :: "r"(dst), "l"(src))
#define CP_COMMIT() asm volatile("cp.async.commit_group;")
#define CP_WAIT1()  asm volatile("cp.async.wait_group 1;")
#define CP_WAIT0()  asm volatile("cp.async.wait_group 0;")

#define LDSM4(r0, r1, r2, r3, addr) \
    asm volatile("ldmatrix.sync.aligned.m8n8.x4.shared.b16 {%0,%1,%2,%3}, [%4];" \
        : "=r"(r0), "=r"(r1), "=r"(r2), "=r"(r3) : "r"(addr))
#define LDSM4T(r0, r1, r2, r3, addr) \
    asm volatile("ldmatrix.sync.aligned.m8n8.x4.trans.shared.b16 {%0,%1,%2,%3}, [%4];" \
        : "=r"(r0), "=r"(r1), "=r"(r2), "=r"(r3) : "r"(addr))

#define MMA16816(d, a, b) \
    asm volatile("mma.sync.aligned.m16n8k16.row.col.f32.f16.f16.f32 " \
        "{%0,%1,%2,%3}, {%4,%5,%6,%7}, {%8,%9}, {%0,%1,%2,%3};" \
        : "+f"((d)[0]), "+f"((d)[1]), "+f"((d)[2]), "+f"((d)[3]) \
        : "r"((a)[0]), "r"((a)[1]), "r"((a)[2]), "r"((a)[3]), \
          "r"((b)[0]), "r"((b)[1]))

// ---------------------------------------------------------------------------
// convert fp32 -> fp16 (straight, coalesced)
// ---------------------------------------------------------------------------
__global__ __launch_bounds__(256) void conv_f16(
    const float* __restrict__ x, __half* __restrict__ hi, int n4)
{
    int i = blockIdx.x * blockDim.x + threadIdx.x;
    if (i >= n4) return;
    float4 v = ((const float4*)x)[i];
    __half h[4] = {__float2half(v.x), __float2half(v.y),
                   __float2half(v.z), __float2half(v.w)};
    ((uint2*)hi)[i] = *(uint2*)h;
}

// ---------------------------------------------------------------------------
// RoPE cos/sin table: tab[(s*32+d)*2] = cos(s*inv_d), +1 = sin
// ---------------------------------------------------------------------------
__global__ __launch_bounds__(256) void rope_table(float* __restrict__ tab)
{
    int i = blockIdx.x * 256 + threadIdx.x;    // 65536
    int s = i >> 5, d = i & 31;
    float inv = powf(10000.f, -(float)d / 32.f);
    float sv, cv; sincosf((float)s * inv, &sv, &cv);
    tab[i * 2] = cv;
    tab[i * 2 + 1] = sv;
}

// ---------------------------------------------------------------------------
// Shared GEMM mainloop. A[M,K] row-major fp16, B[K,N] row-major fp16.
// CTA 128x128, KB=32, 3-stage cp.async. B fragments via ldmatrix.trans.
// B tile: 32 rows x 256B, pitch 272B.
// ---------------------------------------------------------------------------
#define A_BYTES 8192
#define B_PITCH 272
#define B_BYTES (32 * B_PITCH)          // 8704
#define STAGE_BYTES (A_BYTES + B_BYTES) // 16896
#define GEMM_SMEM (3 * STAGE_BYTES)     // 50688

__device__ __forceinline__ void load_stage(
    uint32_t sbase, int stage,
    const __half* __restrict__ A, const __half* __restrict__ Bm,
    int m0, int n0, int k0, int N, int K, int tid)
{
    uint32_t base = sbase + stage * STAGE_BYTES;
    // A: 128 rows x 64B, swizzled (512 chunks)
#pragma unroll
    for (int h = 0; h < 2; h++) {
        int q = tid + h * 256;
        int r = q >> 2, c = q & 3;
        CP_ASYNC16(base + SWZ(r, c), A + (size_t)(m0 + r) * K + k0 + c * 8);
    }
    // B: 32 rows x 256B, pitch 272 (512 chunks: 32 rows x 16 chunks)
#pragma unroll
    for (int h = 0; h < 2; h++) {
        int q = tid + h * 256;
        int r = q >> 4, c = q & 15;
        CP_ASYNC16(base + A_BYTES + r * B_PITCH + c * 16,
                   Bm + (size_t)(k0 + r) * N + n0 + c * 8);
    }
}

__device__ __forceinline__ void gemm_mainloop(
    uint32_t sb, float acc[2][8][4],
    const __half* __restrict__ A, const __half* __restrict__ Bm,
    int m0, int n0, int N, int K, int tid, int wid, int l)
{
    const int wm = (wid & 3) * 32, wnb = (wid >> 2) * 128;  // wnb = n byte offset
    const int niter = K / 32;
    load_stage(sb, 0, A, Bm, m0, n0, 0, N, K, tid);
    CP_COMMIT();
    load_stage(sb, 1, A, Bm, m0, n0, 32, N, K, tid);
    CP_COMMIT();

    int stage = 0;
    for (int j = 0; j < niter; j++) {
        CP_WAIT1();
        __syncthreads();
        if (j + 2 < niter) {
            int s2 = stage + 2; if (s2 >= 3) s2 -= 3;
            load_stage(sb, s2, A, Bm, m0, n0, (j + 2) * 32, N, K, tid);
        }
        CP_COMMIT();

        const uint32_t abase = sb + stage * STAGE_BYTES;
        const uint32_t bbase = abase + A_BYTES;

#pragma unroll
        for (int kk = 0; kk < 2; kk++) {
            uint32_t a_f[2][4];
#pragma unroll
            for (int mi = 0; mi < 2; mi++) {
                int row = wm + mi * 16 + (l & 15);
                int c = kk * 2 + (l >> 4);
                LDSM4(a_f[mi][0], a_f[mi][1], a_f[mi][2], a_f[mi][3],
                      abase + SWZ(row, c));
            }
            uint32_t b_f[8][2];
            {
                int row = kk * 16 + (l & 7) + ((l >> 3) & 1) * 8;
                uint32_t rb = (uint32_t)(row * B_PITCH) + wnb + (l >> 4) * 16;
#pragma unroll
                for (int g2 = 0; g2 < 4; g2++) {
                    LDSM4T(b_f[g2 * 2][0], b_f[g2 * 2][1],
                           b_f[g2 * 2 + 1][0], b_f[g2 * 2 + 1][1],
                           bbase + rb + g2 * 32);
                }
            }
#pragma unroll
            for (int mi = 0; mi < 2; mi++)
#pragma unroll
                for (int nj = 0; nj < 8; nj++)
                    MMA16816(acc[mi][nj], a_f[mi], b_f[nj]);
        }
        stage++; if (stage >= 3) stage -= 3;
    }
}

// ---------------------------------------------------------------------------
// GEMM2: out = gate @ Wt + bias + resid  (plain fp32 epilogue)
// ---------------------------------------------------------------------------
__global__ __launch_bounds__(256) void gemm_hmma(
    const __half* __restrict__ A, const __half* __restrict__ Bm,
    const float* __restrict__ bias, const float* __restrict__ resid,
    float* __restrict__ C, int N, int K)
{
    extern __shared__ char sm[];
    const uint32_t sb = smem_u32(sm);
    const int tid = threadIdx.x, wid = tid >> 5, l = tid & 31;
    const int m0 = blockIdx.y * 128, n0 = blockIdx.x * 128;
    const int wm = (wid & 3) * 32, wn = (wid >> 2) * 64;

    float acc[2][8][4] = {};
    gemm_mainloop(sb, acc, A, Bm, m0, n0, N, K, tid, wid, l);

#pragma unroll
    for (int mi = 0; mi < 2; mi++) {
#pragma unroll
        for (int nj = 0; nj < 8; nj++) {
            int row0 = m0 + wm + mi * 16 + (l >> 2);
            int col  = n0 + wn + nj * 8 + (l & 3) * 2;
            float bx = bias[col], by = bias[col + 1];
            {
                size_t o = (size_t)row0 * N + col;
                float2 v = {acc[mi][nj][0] + bx, acc[mi][nj][1] + by};
                if (resid) { float2 r = *(const float2*)(resid + o); v.x += r.x; v.y += r.y; }
                *(float2*)(C + o) = v;
            }
            {
                size_t o = (size_t)(row0 + 8) * N + col;
                float2 v = {acc[mi][nj][2] + bx, acc[mi][nj][3] + by};
                if (resid) { float2 r = *(const float2*)(resid + o); v.x += r.x; v.y += r.y; }
                *(float2*)(C + o) = v;
            }
        }
    }
}

// ---------------------------------------------------------------------------
// GEMM1 (proj) with fused epilogue (U fp32 / V fp16 / Q,K RoPE+fp16 repack).
// RoPE cos/sin from precomputed table (identical math).
// ---------------------------------------------------------------------------
__global__ __launch_bounds__(256) void gemm_proj(
    const __half* __restrict__ A, const __half* __restrict__ Bm,
    const float* __restrict__ bias, const float* __restrict__ rope,
    float* __restrict__ Ubuf,
    __half* __restrict__ qh, __half* __restrict__ kh, __half* __restrict__ vh,
    int N, int K)
{
    extern __shared__ char sm[];
    const uint32_t sb = smem_u32(sm);
    const int tid = threadIdx.x, wid = tid >> 5, l = tid & 31;
    const int m0 = blockIdx.y * 128, n0 = blockIdx.x * 128;
    const int wm = (wid & 3) * 32, wn = (wid >> 2) * 64;

    float acc[2][8][4] = {};
    gemm_mainloop(sb, acc, A, Bm, m0, n0, N, K, tid, wid, l);

    const int region = n0 >> 10;           // whole CTA in one region

    if (region == 0) {
        // ---- U: fp32 store ----
#pragma unroll
        for (int mi = 0; mi < 2; mi++)
#pragma unroll
            for (int nj = 0; nj < 8; nj++) {
                int row0 = m0 + wm + mi * 16 + (l >> 2);
                int col  = n0 + wn + nj * 8 + (l & 3) * 2;
                float bx = bias[col], by = bias[col + 1];
                *(float2*)(Ubuf + (size_t)row0 * 1024 + col) =
                    make_float2(acc[mi][nj][0] + bx, acc[mi][nj][1] + by);
                *(float2*)(Ubuf + (size_t)(row0 + 8) * 1024 + col) =
                    make_float2(acc[mi][nj][2] + bx, acc[mi][nj][3] + by);
            }
    } else if (region == 1) {
        // ---- V: fp16 repack ----
#pragma unroll
        for (int mi = 0; mi < 2; mi++)
#pragma unroll
            for (int nj = 0; nj < 8; nj++) {
                int col = n0 + wn + nj * 8 + (l & 3) * 2;
                int hd = col & 1023, h = hd >> 6, d = hd & 63;
                float bx = bias[col], by = bias[col + 1];
#pragma unroll
                for (int half = 0; half < 2; half++) {
                    int r = m0 + wm + mi * 16 + (l >> 2) + half * 8;
                    int b = r >> 11, s = r & 2047;
                    __half hv[2] = {__float2half(acc[mi][nj][half * 2] + bx),
                                    __float2half(acc[mi][nj][half * 2 + 1] + by)};
                    size_t o = ((size_t)(b * 16 + h) * 2048 + s) * 64 + d;
                    *(uint32_t*)(vh + o) = *(uint32_t*)hv;
                }
            }
    } else {
        // ---- Q or K: bias + RoPE(table) + fp16 repack ----
        const bool isQ = (region == 2);
        __half* dst = isQ ? qh : kh;
        const float scale = isQ ? 0.125f : 1.0f;
#pragma unroll
        for (int mi = 0; mi < 2; mi++)
#pragma unroll
            for (int nj = 0; nj < 4; nj++) {
                int colA = n0 + wn + nj * 8 + (l & 3) * 2;   // d < 32
                int colB = colA + 32;
                int hd = colA & 1023, h = hd >> 6, d = hd & 63;
                float b1a = bias[colA], b1b = bias[colA + 1];
                float b2a = bias[colB], b2b = bias[colB + 1];
#pragma unroll
                for (int half = 0; half < 2; half++) {
                    int r = m0 + wm + mi * 16 + (l >> 2) + half * 8;
                    int b = r >> 11, s = r & 2047;
                    // {cos_d, sin_d, cos_{d+1}, sin_{d+1}}
                    float4 t = *(const float4*)(rope + ((size_t)(s * 32 + d)) * 2);
                    float x1a = acc[mi][nj][half * 2]     + b1a;
                    float x1b = acc[mi][nj][half * 2 + 1] + b1b;
                    float x2a = acc[mi][nj + 4][half * 2]     + b2a;
                    float x2b = acc[mi][nj + 4][half * 2 + 1] + b2b;
                    __half lo[2] = {__float2half((x1a * t.x - x2a * t.y) * scale),
                                    __float2half((x1b * t.z - x2b * t.w) * scale)};
                    __half hi2[2] = {__float2half((x2a * t.x + x1a * t.y) * scale),
                                     __float2half((x2b * t.z + x1b * t.w) * scale)};
                    size_t o = ((size_t)(b * 16 + h) * 2048 + s) * 64 + d;
                    *(uint32_t*)(dst + o)      = *(uint32_t*)lo;
                    *(uint32_t*)(dst + o + 32) = *(uint32_t*)hi2;
                }
            }
    }
}

// ---------------------------------------------------------------------------
// HMMA sigmoid attention, fp16, 128-row Q tile. 8 warps (4q x 2kv).
// Pitch 144 B rows -> conflict-free ldmatrix. smem 55296.
// ---------------------------------------------------------------------------
#define OQ2 0
#define OK2 18432
#define OV2 27648
#define OP2 36864
#define ATTN_SMEM (55296)

__global__ __launch_bounds__(256) void attn_hmma(
    const __half* __restrict__ qh, const __half* __restrict__ kh,
    const __half* __restrict__ vh, float* __restrict__ out)
{
    extern __shared__ char sm[];
    const uint32_t sb = smem_u32(sm);
    const int tid = threadIdx.x, wid = tid >> 5, l = tid & 31;
    const int bh = blockIdx.x;
    const int qbi = (int)gridDim.y - 1 - (int)blockIdx.y;   // big blocks first
    const int q0 = qbi * 128;
    const size_t hbase = (size_t)bh << 17;                  // bh * 2048 * 64
    const int wq = wid & 3, wn = wid >> 2;

    // ---- load Q tile (128 x 64 fp16) ----
#pragma unroll
    for (int it = 0; it < 4; it++) {
        int i = tid + it * 256;            // 1024 chunks
        int r = i >> 3, c = i & 7;
        uint32_t so = (uint32_t)(r * 144 + c * 16);
        size_t g = hbase + (size_t)(q0 + r) * 64 + c * 8;
        CP_ASYNC16(sb + OQ2 + so, qh + g);
    }
    CP_COMMIT();
    CP_WAIT0();
    __syncthreads();

    float accO[2][4][4] = {};
    const int nkb = 2 * qbi + 2;

    for (int kb = 0; kb < nkb; kb++) {
        const int k0 = kb * 64;
        // ---- load K/V tiles ----
#pragma unroll
        for (int it = 0; it < 2; it++) {
            int i = tid + it * 256;
            int r = i >> 3, c = i & 7;
            uint32_t so = (uint32_t)(r * 144 + c * 16);
            size_t g = hbase + (size_t)(k0 + r) * 64 + c * 8;
            CP_ASYNC16(sb + OK2 + so, kh + g);
            CP_ASYNC16(sb + OV2 + so, vh + g);
        }
        CP_COMMIT();
        CP_WAIT0();
        __syncthreads();

        // ---- scores: Q @ K^T ----
        float sc[2][4][4] = {};
#pragma unroll
        for (int ks = 0; ks < 4; ks++) {
            uint32_t aQ[2][4];
#pragma unroll
            for (int mi = 0; mi < 2; mi++) {
                uint32_t ro = (uint32_t)((wq * 32 + mi * 16 + (l & 15)) * 144 +
                                         (ks * 2 + (l >> 4)) * 16);
                LDSM4(aQ[mi][0], aQ[mi][1], aQ[mi][2], aQ[mi][3], sb + OQ2 + ro);
            }
            uint32_t bK[4][2];
#pragma unroll
            for (int g2 = 0; g2 < 2; g2++) {
                int row = wn * 32 + g2 * 16 + ((l >> 4) * 8) + (l & 7);
                uint32_t ro = (uint32_t)(row * 144 + (ks * 2 + ((l >> 3) & 1)) * 16);
                LDSM4(bK[g2 * 2][0], bK[g2 * 2][1], bK[g2 * 2 + 1][0], bK[g2 * 2 + 1][1],
                      sb + OK2 + ro);
            }
#pragma unroll
            for (int mi = 0; mi < 2; mi++)
#pragma unroll
                for (int nt = 0; nt < 4; nt++) MMA16816(sc[mi][nt], aQ[mi], bK[nt]);
        }

        // ---- sigmoid + causal mask + fp16 P to smem ----
        const bool edge = (kb >= 2 * qbi);
#pragma unroll
        for (int mi = 0; mi < 2; mi++) {
#pragma unroll
            for (int nt = 0; nt < 4; nt++) {
#pragma unroll
                for (int half = 0; half < 2; half++) {
                    int lq = wq * 32 + mi * 16 + (l >> 2) + half * 8;
                    int lk = wn * 32 + nt * 8 + (l & 3) * 2;
                    float p0 = __fdividef(1.f, 1.f + __expf(-sc[mi][nt][half * 2]));
                    float p1 = __fdividef(1.f, 1.f + __expf(-sc[mi][nt][half * 2 + 1]));
                    if (edge) {
                        if (k0 + lk > q0 + lq) p0 = 0.f;
                        if (k0 + lk + 1 > q0 + lq) p1 = 0.f;
                    }
                    __half hp[2] = {__float2half(p0), __float2half(p1)};
                    *(uint32_t*)(sm + OP2 + (uint32_t)(lq * 144 + lk * 2)) = *(uint32_t*)hp;
                }
            }
        }
        __syncthreads();

        // ---- O += P @ V ----
#pragma unroll
        for (int ks = 0; ks < 4; ks++) {
            uint32_t aP[2][4];
#pragma unroll
            for (int mi = 0; mi < 2; mi++) {
                uint32_t ro = (uint32_t)((wq * 32 + mi * 16 + (l & 15)) * 144 +
                                         (ks * 2 + (l >> 4)) * 16);
                LDSM4(aP[mi][0], aP[mi][1], aP[mi][2], aP[mi][3], sb + OP2 + ro);
            }
            uint32_t bV[4][2];
#pragma unroll
            for (int g2 = 0; g2 < 2; g2++) {
                int row = ks * 16 + (l & 7) + ((l >> 3) & 1) * 8;
                uint32_t ro = (uint32_t)(row * 144 + wn * 64 + g2 * 32 + (l >> 4) * 16);
                LDSM4T(bV[g2 * 2][0], bV[g2 * 2][1], bV[g2 * 2 + 1][0], bV[g2 * 2 + 1][1],
                       sb + OV2 + ro);
            }
#pragma unroll
            for (int mi = 0; mi < 2; mi++)
#pragma unroll
                for (int dt = 0; dt < 4; dt++) MMA16816(accO[mi][dt], aP[mi], bV[dt]);
        }
        __syncthreads();
    }

    // ---- epilogue ----
    const int b = bh >> 4, h = bh & 15;
#pragma unroll
    for (int mi = 0; mi < 2; mi++) {
#pragma unroll
        for (int dt = 0; dt < 4; dt++) {
#pragma unroll
            for (int half = 0; half < 2; half++) {
                int q = q0 + wq * 32 + mi * 16 + (l >> 2) + half * 8;
                int d = wn * 32 + dt * 8 + (l & 3) * 2;
                size_t o = ((size_t)(b * 2048 + q)) * 1024 + h * 64 + d;
                float2 v = {accO[mi][dt][half * 2], accO[mi][dt][half * 2 + 1]};
                *(float2*)(out + o) = v;
            }
        }
    }
}

// ---------------------------------------------------------------------------
// Fused LayerNorm + SiLU(U) gate -> fp16  (U already has bias applied)
// ---------------------------------------------------------------------------
__global__ __launch_bounds__(256) void ln_gate_kernel(
    const float* __restrict__ attn, const float* __restrict__ Ubuf,
    const float* __restrict__ g, const float* __restrict__ bb,
    __half* __restrict__ gh)
{
    const int row = blockIdx.x;
    const int tid = threadIdx.x;
    const float* a = attn + (size_t)row * H_;

    float s = 0.f, s2 = 0.f;
    for (int i = tid; i < H_; i += 256) {
        float v = a[i];
        s += v;
        s2 = fmaf(v, v, s2);
    }
    __shared__ float red[2][8];
#pragma unroll
    for (int o = 16; o; o >>= 1) {
        s  += __shfl_xor_sync(~0u, s,  o);
        s2 += __shfl_xor_sync(~0u, s2, o);
    }
    if ((tid & 31) == 0) { red[0][tid >> 5] = s; red[1][tid >> 5] = s2; }
    __syncthreads();
    if (tid < 32) {
        s  = (tid < 8) ? red[0][tid] : 0.f;
        s2 = (tid < 8) ? red[1][tid] : 0.f;
#pragma unroll
        for (int o = 4; o; o >>= 1) {
            s  += __shfl_xor_sync(~0u, s,  o);
            s2 += __shfl_xor_sync(~0u, s2, o);
        }
        if (tid == 0) { red[0][0] = s; red[1][0] = s2; }
    }
    __syncthreads();
    const float mu  = red[0][0] * (1.f / H_);
    const float var = red[1][0] * (1.f / H_) - mu * mu;
    const float rstd = rsqrtf(var + 1e-8f);

    const float* up = Ubuf + (size_t)row * H_;
    for (int i = tid; i < H_; i += 256) {
        float u = up[i];
        float silu = u * __fdividef(1.f, 1.f + __expf(-u));
        float v = silu * ((a[i] - mu) * rstd * g[i] + bb[i]);
        gh[(size_t)row * H_ + i] = __float2half(v);
    }
}

// ---------------------------------------------------------------------------
extern "C" void kernel_launch(void* const* d_in, const int* in_sizes, int n_in,
                              void* d_out, int out_size)
{
    const float* x   = (const float*)d_in[0];
    const float* Wp  = (const float*)d_in[2];
    const float* bp  = (const float*)d_in[3];
    const float* lng = (const float*)d_in[4];
    const float* lnb = (const float*)d_in[5];
    const float* Wt  = (const float*)d_in[6];
    const float* bt  = (const float*)d_in[7];
    float* out = (float*)d_out;

    float *Ubuf, *attn, *rope;
    __half *xh, *gh, *Wp16, *Wt16, *aqh, *akh, *avh;
    cudaGetSymbolAddress((void**)&Ubuf, g_U);
    cudaGetSymbolAddress((void**)&attn, g_attn);
    cudaGetSymbolAddress((void**)&rope, g_rope);
    cudaGetSymbolAddress((void**)&xh, g_xh);
    cudaGetSymbolAddress((void**)&gh, g_gh);
    cudaGetSymbolAddress((void**)&Wp16, g_Wp16);
    cudaGetSymbolAddress((void**)&Wt16, g_Wt16);
    cudaGetSymbolAddress((void**)&aqh, g_qh);
    cudaGetSymbolAddress((void**)&akh, g_kh);
    cudaGetSymbolAddress((void**)&avh, g_vh);

    cudaFuncSetAttribute(gemm_hmma,
                         cudaFuncAttributeMaxDynamicSharedMemorySize, GEMM_SMEM);
    cudaFuncSetAttribute(gemm_proj,
                         cudaFuncAttributeMaxDynamicSharedMemorySize, GEMM_SMEM);
    cudaFuncSetAttribute(attn_hmma,
                         cudaFuncAttributeMaxDynamicSharedMemorySize, ATTN_SMEM);

    // 0) converts (straight, no transpose) + rope table
    conv_f16<<<(M_ * H_ / 4 + 255) / 256, 256>>>(x, xh, M_ * H_ / 4);
    conv_f16<<<(4 * H_ * H_ / 4 + 255) / 256, 256>>>(Wp, Wp16, 4 * H_ * H_ / 4);
    conv_f16<<<(H_ * H_ / 4 + 255) / 256, 256>>>(Wt, Wt16, H_ * H_ / 4);
    rope_table<<<2048 * 32 / 256, 256>>>(rope);

    // 1) proj GEMM with fused bias + RoPE + fp16 repack epilogue
    gemm_proj<<<dim3(4 * H_ / 128, M_ / 128), 256, GEMM_SMEM>>>(
        xh, Wp16, bp, rope, Ubuf, aqh, akh, avh, 4 * H_, H_);

    // 2) HMMA sigmoid attention -> attn [8192, 1024]
    attn_hmma<<<dim3(B_ * NH, S_ / 128), 256, ATTN_SMEM>>>(aqh, akh, avh, attn);

    // 3) LN + SiLU gate -> fp16
    ln_gate_kernel<<<M_, 256>>>(attn, Ubuf, lng, lnb, gh);

    // 4) out = x + gate @ Wt + bt
    gemm_hmma<<<dim3(H_ / 128, M_ / 128), 256, GEMM_SMEM>>>(
        gh, Wt16, bt, x, out, H_, H_);
}

// round 15
// speedup vs baseline: 1.0040x; 1.0040x over previous
#include <cuda_runtime.h>
#include <cuda_fp16.h>
#include <math.h>
#include <stdint.h>

#define B_  4
#define S_  2048
#define H_  1024
#define NH  16
#define M_  (B_ * S_)          // 8192 rows

// ------------------------- scratch (__device__ globals) --------------------
__device__ float g_U[(size_t)M_ * H_];                 // 32 MB : U (fp32, biased)
__device__ float g_attn[(size_t)M_ * H_];              // 32 MB
__device__ __half g_xh[(size_t)M_ * H_];
__device__ __half g_gh[(size_t)M_ * H_];
__device__ __half g_WpT[(size_t)4 * H_ * H_];          // Wp^T [4096,1024] fp16
__device__ __half g_WtT[(size_t)H_ * H_];              // Wt^T [1024,1024] fp16
__device__ float g_rope[2048 * 32 * 2];                // cos,sin table
// attention operands in [b*h][s][64] layout
__device__ __half g_qh[(size_t)M_ * H_];
__device__ __half g_kh[(size_t)M_ * H_];
__device__ __half g_vh[(size_t)M_ * H_];

// ------------------------- helpers -----------------------------------------
__device__ __forceinline__ uint32_t smem_u32(const void* p) {
    uint32_t a;
    asm("{ .reg .u64 t; cvta.to.shared.u64 t, %1; cvt.u32.u64 %0, t; }"
        : "=r"(a) : "l"(p));
    return a;
}

#define SWZ(r, c) ((uint32_t)((r) * 64 + (((c) ^ (((r) >> 1) & 3)) * 16)))

#define CP_ASYNC16(dst, src) \
    asm volatile("cp.async.cg.shared.global [%0], [%1], 16;" :: "r"(dst), "l"(src))
#define CP_COMMIT() asm volatile("cp.async.commit_group;")
#define CP_WAIT1()  asm volatile("cp.async.wait_group 1;")
#define CP_WAIT0()  asm volatile("cp.async.wait_group 0;")

#define LDSM4(r0, r1, r2, r3, addr) \
    asm volatile("ldmatrix.sync.aligned.m8n8.x4.shared.b16 {%0,%1,%2,%3}, [%4];" \
        : "=r"(r0), "=r"(r1), "=r"(r2), "=r"(r3) : "r"(addr))
#define LDSM4T(r0, r1, r2, r3, addr) \
    asm volatile("ldmatrix.sync.aligned.m8n8.x4.trans.shared.b16 {%0,%1,%2,%3}, [%4];" \
        : "=r"(r0), "=r"(r1), "=r"(r2), "=r"(r3) : "r"(addr))

#define MMA16816(d, a, b) \
    asm volatile("mma.sync.aligned.m16n8k16.row.col.f32.f16.f16.f32 " \
        "{%0,%1,%2,%3}, {%4,%5,%6,%7}, {%8,%9}, {%0,%1,%2,%3};" \
        : "+f"((d)[0]), "+f"((d)[1]), "+f"((d)[2]), "+f"((d)[3]) \
        : "r"((a)[0]), "r"((a)[1]), "r"((a)[2]), "r"((a)[3]), \
          "r"((b)[0]), "r"((b)[1]))

// ---------------------------------------------------------------------------
// convert fp32 -> fp16 (straight, coalesced)
// ---------------------------------------------------------------------------
__global__ __launch_bounds__(256) void conv_f16(
    const float* __restrict__ x, __half* __restrict__ hi, int n4)
{
    int i = blockIdx.x * blockDim.x + threadIdx.x;
    if (i >= n4) return;
    float4 v = ((const float4*)x)[i];
    __half h[4] = {__float2half(v.x), __float2half(v.y),
                   __float2half(v.z), __float2half(v.w)};
    ((uint2*)hi)[i] = *(uint2*)h;
}

// ---------------------------------------------------------------------------
// transpose W[K,N] -> WT[N,K] fp16
// ---------------------------------------------------------------------------
__global__ __launch_bounds__(256) void transpose_half(
    const float* __restrict__ W, __half* __restrict__ T, int K, int N)
{
    __shared__ float t[32][33];
    const int tx = threadIdx.x, ty = threadIdx.y;
    const int n0 = blockIdx.x * 32, k0 = blockIdx.y * 32;
#pragma unroll
    for (int j = 0; j < 32; j += 8)
        t[ty + j][tx] = W[(size_t)(k0 + ty + j) * N + n0 + tx];
    __syncthreads();
#pragma unroll
    for (int j = 0; j < 32; j += 8)
        T[(size_t)(n0 + ty + j) * K + k0 + tx] = __float2half(t[tx][ty + j]);
}

// ---------------------------------------------------------------------------
// RoPE cos/sin table: tab[(s*32+d)*2] = cos(s*inv_d), +1 = sin
// ---------------------------------------------------------------------------
__global__ __launch_bounds__(256) void rope_table(float* __restrict__ tab)
{
    int i = blockIdx.x * 256 + threadIdx.x;    // 65536
    int s = i >> 5, d = i & 31;
    float inv = powf(10000.f, -(float)d / 32.f);
    float sv, cv; sincosf((float)s * inv, &sv, &cv);
    tab[i * 2] = cv;
    tab[i * 2 + 1] = sv;
}

// ---------------------------------------------------------------------------
// Shared GEMM mainloop (R10/R12 proven version): A[M,K], B^T[N,K] both
// K-major fp16. CTA 128x128, KB=32, 3-stage cp.async.
// ---------------------------------------------------------------------------
#define STAGE_BYTES 16384
#define OFF_A 0
#define OFF_B 8192
#define GEMM_SMEM (3 * STAGE_BYTES)     // 49152

__device__ __forceinline__ void load_stage(
    uint32_t sbase, int stage,
    const __half* __restrict__ A, const __half* __restrict__ Bm,
    int m0, int n0, int k0, int K, int tid)
{
    uint32_t base = sbase + stage * STAGE_BYTES;
#pragma unroll
    for (int h = 0; h < 2; h++) {
        int q = tid + h * 256;
        int r = q >> 2, c = q & 3;
        uint32_t so = SWZ(r, c);
        size_t ga = (size_t)(m0 + r) * K + k0 + c * 8;
        size_t gb = (size_t)(n0 + r) * K + k0 + c * 8;
        CP_ASYNC16(base + OFF_A + so, A + ga);
        CP_ASYNC16(base + OFF_B + so, Bm + gb);
    }
}

__device__ __forceinline__ void gemm_mainloop(
    uint32_t sb, float acc[2][8][4],
    const __half* __restrict__ A, const __half* __restrict__ Bm,
    int m0, int n0, int K, int tid, int wid, int l)
{
    const int wm = (wid & 3) * 32, wn = (wid >> 2) * 64;
    const int niter = K / 32;
    load_stage(sb, 0, A, Bm, m0, n0, 0, K, tid);
    CP_COMMIT();
    load_stage(sb, 1, A, Bm, m0, n0, 32, K, tid);
    CP_COMMIT();

    int stage = 0;
    for (int j = 0; j < niter; j++) {
        CP_WAIT1();
        __syncthreads();
        if (j + 2 < niter) {
            int s2 = stage + 2; if (s2 >= 3) s2 -= 3;
            load_stage(sb, s2, A, Bm, m0, n0, (j + 2) * 32, K, tid);
        }
        CP_COMMIT();

        const uint32_t base = sb + stage * STAGE_BYTES;
        const uint32_t abase = base + OFF_A;
        const uint32_t bbase = base + OFF_B;

#pragma unroll
        for (int kk = 0; kk < 2; kk++) {
            uint32_t a_f[2][4];
#pragma unroll
            for (int mi = 0; mi < 2; mi++) {
                int row = wm + mi * 16 + (l & 15);
                int c = kk * 2 + (l >> 4);
                LDSM4(a_f[mi][0], a_f[mi][1], a_f[mi][2], a_f[mi][3],
                      abase + SWZ(row, c));
            }
            uint32_t b_f[8][2];
#pragma unroll
            for (int p = 0; p < 4; p++) {
                int row = wn + p * 16 + ((l >> 4) * 8) + (l & 7);
                int c = kk * 2 + ((l >> 3) & 1);
                LDSM4(b_f[p * 2][0], b_f[p * 2][1], b_f[p * 2 + 1][0], b_f[p * 2 + 1][1],
                      bbase + SWZ(row, c));
            }
#pragma unroll
            for (int mi = 0; mi < 2; mi++)
#pragma unroll
                for (int nj = 0; nj < 8; nj++)
                    MMA16816(acc[mi][nj], a_f[mi], b_f[nj]);
        }
        stage++; if (stage >= 3) stage -= 3;
    }
}

// ---------------------------------------------------------------------------
// GEMM2: out = gate @ WtT^T + bias + resid  (plain fp32 epilogue)
// ---------------------------------------------------------------------------
__global__ __launch_bounds__(256) void gemm_hmma(
    const __half* __restrict__ A, const __half* __restrict__ Bm,
    const float* __restrict__ bias, const float* __restrict__ resid,
    float* __restrict__ C, int N, int K)
{
    extern __shared__ char sm[];
    const uint32_t sb = smem_u32(sm);
    const int tid = threadIdx.x, wid = tid >> 5, l = tid & 31;
    const int m0 = blockIdx.y * 128, n0 = blockIdx.x * 128;
    const int wm = (wid & 3) * 32, wn = (wid >> 2) * 64;

    float acc[2][8][4] = {};
    gemm_mainloop(sb, acc, A, Bm, m0, n0, K, tid, wid, l);

#pragma unroll
    for (int mi = 0; mi < 2; mi++) {
#pragma unroll
        for (int nj = 0; nj < 8; nj++) {
            int row0 = m0 + wm + mi * 16 + (l >> 2);
            int col  = n0 + wn + nj * 8 + (l & 3) * 2;
            float bx = bias[col], by = bias[col + 1];
            {
                size_t o = (size_t)row0 * N + col;
                float2 v = {acc[mi][nj][0] + bx, acc[mi][nj][1] + by};
                if (resid) { float2 r = *(const float2*)(resid + o); v.x += r.x; v.y += r.y; }
                *(float2*)(C + o) = v;
            }
            {
                size_t o = (size_t)(row0 + 8) * N + col;
                float2 v = {acc[mi][nj][2] + bx, acc[mi][nj][3] + by};
                if (resid) { float2 r = *(const float2*)(resid + o); v.x += r.x; v.y += r.y; }
                *(float2*)(C + o) = v;
            }
        }
    }
}

// ---------------------------------------------------------------------------
// GEMM1 (proj) with fused epilogue (U fp32 / V fp16 / Q,K RoPE+fp16 repack).
// RoPE cos/sin from precomputed table (identical math to sincosf).
// ---------------------------------------------------------------------------
__global__ __launch_bounds__(256) void gemm_proj(
    const __half* __restrict__ A, const __half* __restrict__ Bm,
    const float* __restrict__ bias, const float* __restrict__ rope,
    float* __restrict__ Ubuf,
    __half* __restrict__ qh, __half* __restrict__ kh, __half* __restrict__ vh,
    int N, int K)
{
    extern __shared__ char sm[];
    const uint32_t sb = smem_u32(sm);
    const int tid = threadIdx.x, wid = tid >> 5, l = tid & 31;
    const int m0 = blockIdx.y * 128, n0 = blockIdx.x * 128;
    const int wm = (wid & 3) * 32, wn = (wid >> 2) * 64;

    float acc[2][8][4] = {};
    gemm_mainloop(sb, acc, A, Bm, m0, n0, K, tid, wid, l);

    const int region = n0 >> 10;           // whole CTA in one region

    if (region == 0) {
        // ---- U: fp32 store ----
#pragma unroll
        for (int mi = 0; mi < 2; mi++)
#pragma unroll
            for (int nj = 0; nj < 8; nj++) {
                int row0 = m0 + wm + mi * 16 + (l >> 2);
                int col  = n0 + wn + nj * 8 + (l & 3) * 2;
                float bx = bias[col], by = bias[col + 1];
                *(float2*)(Ubuf + (size_t)row0 * 1024 + col) =
                    make_float2(acc[mi][nj][0] + bx, acc[mi][nj][1] + by);
                *(float2*)(Ubuf + (size_t)(row0 + 8) * 1024 + col) =
                    make_float2(acc[mi][nj][2] + bx, acc[mi][nj][3] + by);
            }
    } else if (region == 1) {
        // ---- V: fp16 repack ----
#pragma unroll
        for (int mi = 0; mi < 2; mi++)
#pragma unroll
            for (int nj = 0; nj < 8; nj++) {
                int col = n0 + wn + nj * 8 + (l & 3) * 2;
                int hd = col & 1023, h = hd >> 6, d = hd & 63;
                float bx = bias[col], by = bias[col + 1];
#pragma unroll
                for (int half = 0; half < 2; half++) {
                    int r = m0 + wm + mi * 16 + (l >> 2) + half * 8;
                    int b = r >> 11, s = r & 2047;
                    __half hv[2] = {__float2half(acc[mi][nj][half * 2] + bx),
                                    __float2half(acc[mi][nj][half * 2 + 1] + by)};
                    size_t o = ((size_t)(b * 16 + h) * 2048 + s) * 64 + d;
                    *(uint32_t*)(vh + o) = *(uint32_t*)hv;
                }
            }
    } else {
        // ---- Q or K: bias + RoPE(table) + fp16 repack ----
        const bool isQ = (region == 2);
        __half* dst = isQ ? qh : kh;
        const float scale = isQ ? 0.125f : 1.0f;
#pragma unroll
        for (int mi = 0; mi < 2; mi++)
#pragma unroll
            for (int nj = 0; nj < 4; nj++) {
                int colA = n0 + wn + nj * 8 + (l & 3) * 2;   // d < 32
                int colB = colA + 32;
                int hd = colA & 1023, h = hd >> 6, d = hd & 63;
                float b1a = bias[colA], b1b = bias[colA + 1];
                float b2a = bias[colB], b2b = bias[colB + 1];
#pragma unroll
                for (int half = 0; half < 2; half++) {
                    int r = m0 + wm + mi * 16 + (l >> 2) + half * 8;
                    int b = r >> 11, s = r & 2047;
                    // {cos_d, sin_d, cos_{d+1}, sin_{d+1}}
                    float4 t = *(const float4*)(rope + ((size_t)(s * 32 + d)) * 2);
                    float x1a = acc[mi][nj][half * 2]     + b1a;
                    float x1b = acc[mi][nj][half * 2 + 1] + b1b;
                    float x2a = acc[mi][nj + 4][half * 2]     + b2a;
                    float x2b = acc[mi][nj + 4][half * 2 + 1] + b2b;
                    __half lo[2] = {__float2half((x1a * t.x - x2a * t.y) * scale),
                                    __float2half((x1b * t.z - x2b * t.w) * scale)};
                    __half hi2[2] = {__float2half((x2a * t.x + x1a * t.y) * scale),
                                     __float2half((x2b * t.z + x1b * t.w) * scale)};
                    size_t o = ((size_t)(b * 16 + h) * 2048 + s) * 64 + d;
                    *(uint32_t*)(dst + o)      = *(uint32_t*)lo;
                    *(uint32_t*)(dst + o + 32) = *(uint32_t*)hi2;
                }
            }
    }
}

// ---------------------------------------------------------------------------
// HMMA sigmoid attention, fp16, 128-row Q tile. 8 warps (4q x 2kv).
// Pitch 144 B rows -> conflict-free ldmatrix. smem 55296.
// ---------------------------------------------------------------------------
#define OQ2 0
#define OK2 18432
#define OV2 27648
#define OP2 36864
#define ATTN_SMEM (55296)

__global__ __launch_bounds__(256) void attn_hmma(
    const __half* __restrict__ qh, const __half* __restrict__ kh,
    const __half* __restrict__ vh, float* __restrict__ out)
{
    extern __shared__ char sm[];
    const uint32_t sb = smem_u32(sm);
    const int tid = threadIdx.x, wid = tid >> 5, l = tid & 31;
    const int bh = blockIdx.x;
    const int qbi = (int)gridDim.y - 1 - (int)blockIdx.y;   // big blocks first
    const int q0 = qbi * 128;
    const size_t hbase = (size_t)bh << 17;                  // bh * 2048 * 64
    const int wq = wid & 3, wn = wid >> 2;

    // ---- load Q tile (128 x 64 fp16) ----
#pragma unroll
    for (int it = 0; it < 4; it++) {
        int i = tid + it * 256;            // 1024 chunks
        int r = i >> 3, c = i & 7;
        uint32_t so = (uint32_t)(r * 144 + c * 16);
        size_t g = hbase + (size_t)(q0 + r) * 64 + c * 8;
        CP_ASYNC16(sb + OQ2 + so, qh + g);
    }
    CP_COMMIT();
    CP_WAIT0();
    __syncthreads();

    float accO[2][4][4] = {};
    const int nkb = 2 * qbi + 2;

    for (int kb = 0; kb < nkb; kb++) {
        const int k0 = kb * 64;
        // ---- load K/V tiles ----
#pragma unroll
        for (int it = 0; it < 2; it++) {
            int i = tid + it * 256;
            int r = i >> 3, c = i & 7;
            uint32_t so = (uint32_t)(r * 144 + c * 16);
            size_t g = hbase + (size_t)(k0 + r) * 64 + c * 8;
            CP_ASYNC16(sb + OK2 + so, kh + g);
            CP_ASYNC16(sb + OV2 + so, vh + g);
        }
        CP_COMMIT();
        CP_WAIT0();
        __syncthreads();

        // ---- scores: Q @ K^T ----
        float sc[2][4][4] = {};
#pragma unroll
        for (int ks = 0; ks < 4; ks++) {
            uint32_t aQ[2][4];
#pragma unroll
            for (int mi = 0; mi < 2; mi++) {
                uint32_t ro = (uint32_t)((wq * 32 + mi * 16 + (l & 15)) * 144 +
                                         (ks * 2 + (l >> 4)) * 16);
                LDSM4(aQ[mi][0], aQ[mi][1], aQ[mi][2], aQ[mi][3], sb + OQ2 + ro);
            }
            uint32_t bK[4][2];
#pragma unroll
            for (int g2 = 0; g2 < 2; g2++) {
                int row = wn * 32 + g2 * 16 + ((l >> 4) * 8) + (l & 7);
                uint32_t ro = (uint32_t)(row * 144 + (ks * 2 + ((l >> 3) & 1)) * 16);
                LDSM4(bK[g2 * 2][0], bK[g2 * 2][1], bK[g2 * 2 + 1][0], bK[g2 * 2 + 1][1],
                      sb + OK2 + ro);
            }
#pragma unroll
            for (int mi = 0; mi < 2; mi++)
#pragma unroll
                for (int nt = 0; nt < 4; nt++) MMA16816(sc[mi][nt], aQ[mi], bK[nt]);
        }

        // ---- sigmoid + causal mask + fp16 P to smem ----
        const bool edge = (kb >= 2 * qbi);
#pragma unroll
        for (int mi = 0; mi < 2; mi++) {
#pragma unroll
            for (int nt = 0; nt < 4; nt++) {
#pragma unroll
                for (int half = 0; half < 2; half++) {
                    int lq = wq * 32 + mi * 16 + (l >> 2) + half * 8;
                    int lk = wn * 32 + nt * 8 + (l & 3) * 2;
                    float p0 = __fdividef(1.f, 1.f + __expf(-sc[mi][nt][half * 2]));
                    float p1 = __fdividef(1.f, 1.f + __expf(-sc[mi][nt][half * 2 + 1]));
                    if (edge) {
                        if (k0 + lk > q0 + lq) p0 = 0.f;
                        if (k0 + lk + 1 > q0 + lq) p1 = 0.f;
                    }
                    __half hp[2] = {__float2half(p0), __float2half(p1)};
                    *(uint32_t*)(sm + OP2 + (uint32_t)(lq * 144 + lk * 2)) = *(uint32_t*)hp;
                }
            }
        }
        __syncthreads();

        // ---- O += P @ V ----
#pragma unroll
        for (int ks = 0; ks < 4; ks++) {
            uint32_t aP[2][4];
#pragma unroll
            for (int mi = 0; mi < 2; mi++) {
                uint32_t ro = (uint32_t)((wq * 32 + mi * 16 + (l & 15)) * 144 +
                                         (ks * 2 + (l >> 4)) * 16);
                LDSM4(aP[mi][0], aP[mi][1], aP[mi][2], aP[mi][3], sb + OP2 + ro);
            }
            uint32_t bV[4][2];
#pragma unroll
            for (int g2 = 0; g2 < 2; g2++) {
                int row = ks * 16 + (l & 7) + ((l >> 3) & 1) * 8;
                uint32_t ro = (uint32_t)(row * 144 + wn * 64 + g2 * 32 + (l >> 4) * 16);
                LDSM4T(bV[g2 * 2][0], bV[g2 * 2][1], bV[g2 * 2 + 1][0], bV[g2 * 2 + 1][1],
                       sb + OV2 + ro);
            }
#pragma unroll
            for (int mi = 0; mi < 2; mi++)
#pragma unroll
                for (int dt = 0; dt < 4; dt++) MMA16816(accO[mi][dt], aP[mi], bV[dt]);
        }
        __syncthreads();
    }

    // ---- epilogue ----
    const int b = bh >> 4, h = bh & 15;
#pragma unroll
    for (int mi = 0; mi < 2; mi++) {
#pragma unroll
        for (int dt = 0; dt < 4; dt++) {
#pragma unroll
            for (int half = 0; half < 2; half++) {
                int q = q0 + wq * 32 + mi * 16 + (l >> 2) + half * 8;
                int d = wn * 32 + dt * 8 + (l & 3) * 2;
                size_t o = ((size_t)(b * 2048 + q)) * 1024 + h * 64 + d;
                float2 v = {accO[mi][dt][half * 2], accO[mi][dt][half * 2 + 1]};
                *(float2*)(out + o) = v;
            }
        }
    }
}

// ---------------------------------------------------------------------------
// Fused LayerNorm + SiLU(U) gate -> fp16  (U already has bias applied)
// ---------------------------------------------------------------------------
__global__ __launch_bounds__(256) void ln_gate_kernel(
    const float* __restrict__ attn, const float* __restrict__ Ubuf,
    const float* __restrict__ g, const float* __restrict__ bb,
    __half* __restrict__ gh)
{
    const int row = blockIdx.x;
    const int tid = threadIdx.x;
    const float* a = attn + (size_t)row * H_;

    float s = 0.f, s2 = 0.f;
    for (int i = tid; i < H_; i += 256) {
        float v = a[i];
        s += v;
        s2 = fmaf(v, v, s2);
    }
    __shared__ float red[2][8];
#pragma unroll
    for (int o = 16; o; o >>= 1) {
        s  += __shfl_xor_sync(~0u, s,  o);
        s2 += __shfl_xor_sync(~0u, s2, o);
    }
    if ((tid & 31) == 0) { red[0][tid >> 5] = s; red[1][tid >> 5] = s2; }
    __syncthreads();
    if (tid < 32) {
        s  = (tid < 8) ? red[0][tid] : 0.f;
        s2 = (tid < 8) ? red[1][tid] : 0.f;
#pragma unroll
        for (int o = 4; o; o >>= 1) {
            s  += __shfl_xor_sync(~0u, s,  o);
            s2 += __shfl_xor_sync(~0u, s2, o);
        }
        if (tid == 0) { red[0][0] = s; red[1][0] = s2; }
    }
    __syncthreads();
    const float mu  = red[0][0] * (1.f / H_);
    const float var = red[1][0] * (1.f / H_) - mu * mu;
    const float rstd = rsqrtf(var + 1e-8f);

    const float* up = Ubuf + (size_t)row * H_;
    for (int i = tid; i < H_; i += 256) {
        float u = up[i];
        float silu = u * __fdividef(1.f, 1.f + __expf(-u));
        float v = silu * ((a[i] - mu) * rstd * g[i] + bb[i]);
        gh[(size_t)row * H_ + i] = __float2half(v);
    }
}

// ---------------------------------------------------------------------------
extern "C" void kernel_launch(void* const* d_in, const int* in_sizes, int n_in,
                              void* d_out, int out_size)
{
    const float* x   = (const float*)d_in[0];
    const float* Wp  = (const float*)d_in[2];
    const float* bp  = (const float*)d_in[3];
    const float* lng = (const float*)d_in[4];
    const float* lnb = (const float*)d_in[5];
    const float* Wt  = (const float*)d_in[6];
    const float* bt  = (const float*)d_in[7];
    float* out = (float*)d_out;

    float *Ubuf, *attn, *rope;
    __half *xh, *gh, *WpT, *WtT, *aqh, *akh, *avh;
    cudaGetSymbolAddress((void**)&Ubuf, g_U);
    cudaGetSymbolAddress((void**)&attn, g_attn);
    cudaGetSymbolAddress((void**)&rope, g_rope);
    cudaGetSymbolAddress((void**)&xh, g_xh);
    cudaGetSymbolAddress((void**)&gh, g_gh);
    cudaGetSymbolAddress((void**)&WpT, g_WpT);
    cudaGetSymbolAddress((void**)&WtT, g_WtT);
    cudaGetSymbolAddress((void**)&aqh, g_qh);
    cudaGetSymbolAddress((void**)&akh, g_kh);
    cudaGetSymbolAddress((void**)&avh, g_vh);

    cudaFuncSetAttribute(gemm_hmma,
                         cudaFuncAttributeMaxDynamicSharedMemorySize, GEMM_SMEM);
    cudaFuncSetAttribute(gemm_proj,
                         cudaFuncAttributeMaxDynamicSharedMemorySize, GEMM_SMEM);
    cudaFuncSetAttribute(attn_hmma,
                         cudaFuncAttributeMaxDynamicSharedMemorySize, ATTN_SMEM);

    // 0) convert + weight transposes (K-major path, proven fast) + rope table
    conv_f16<<<(M_ * H_ / 4 + 255) / 256, 256>>>(x, xh, M_ * H_ / 4);
    transpose_half<<<dim3(4 * H_ / 32, H_ / 32), dim3(32, 8)>>>(Wp, WpT, H_, 4 * H_);
    transpose_half<<<dim3(H_ / 32, H_ / 32), dim3(32, 8)>>>(Wt, WtT, H_, H_);
    rope_table<<<2048 * 32 / 256, 256>>>(rope);

    // 1) proj GEMM with fused bias + RoPE(table) + fp16 repack epilogue
    gemm_proj<<<dim3(4 * H_ / 128, M_ / 128), 256, GEMM_SMEM>>>(
        xh, WpT, bp, rope, Ubuf, aqh, akh, avh, 4 * H_, H_);

    // 2) HMMA sigmoid attention -> attn [8192, 1024]
    attn_hmma<<<dim3(B_ * NH, S_ / 128), 256, ATTN_SMEM>>>(aqh, akh, avh, attn);

    // 3) LN + SiLU gate -> fp16
    ln_gate_kernel<<<M_, 256>>>(attn, Ubuf, lng, lnb, gh);

    // 4) out = x + gate @ Wt + bt
    gemm_hmma<<<dim3(H_ / 128, M_ / 128), 256, GEMM_SMEM>>>(
        gh, WtT, bt, x, out, H_, H_);
}

// round 16
// speedup vs baseline: 1.1665x; 1.1618x over previous
#include <cuda_runtime.h>
#include <cuda_fp16.h>
#include <math.h>
#include <stdint.h>

#define B_  4
#define S_  2048
#define H_  1024
#define NH  16
#define M_  (B_ * S_)          // 8192 rows

// ------------------------- scratch (__device__ globals) --------------------
__device__ float g_U[(size_t)M_ * H_];                 // 32 MB : U (fp32, biased)
__device__ float g_attn[(size_t)M_ * H_];              // 32 MB
__device__ __half g_xh[(size_t)M_ * H_];
__device__ __half g_gh[(size_t)M_ * H_];
__device__ __half g_WpT[(size_t)4 * H_ * H_];          // Wp^T [4096,1024] fp16
__device__ __half g_WtT[(size_t)H_ * H_];              // Wt^T [1024,1024] fp16
// attention operands in [b*h][s][64] layout
__device__ __half g_qh[(size_t)M_ * H_];
__device__ __half g_kh[(size_t)M_ * H_];
__device__ __half g_vh[(size_t)M_ * H_];

// ------------------------- helpers -----------------------------------------
__device__ __forceinline__ uint32_t smem_u32(const void* p) {
    uint32_t a;
    asm("{ .reg .u64 t; cvta.to.shared.u64 t, %1; cvt.u32.u64 %0, t; }"
        : "=r"(a) : "l"(p));
    return a;
}

#define SWZ(r, c) ((uint32_t)((r) * 64 + (((c) ^ (((r) >> 1) & 3)) * 16)))

#define CP_ASYNC16(dst, src) \
    asm volatile("cp.async.cg.shared.global [%0], [%1], 16;" :: "r"(dst), "l"(src))
#define CP_COMMIT() asm volatile("cp.async.commit_group;")
#define CP_WAIT1()  asm volatile("cp.async.wait_group 1;")
#define CP_WAIT0()  asm volatile("cp.async.wait_group 0;")

#define LDSM4(r0, r1, r2, r3, addr) \
    asm volatile("ldmatrix.sync.aligned.m8n8.x4.shared.b16 {%0,%1,%2,%3}, [%4];" \
        : "=r"(r0), "=r"(r1), "=r"(r2), "=r"(r3) : "r"(addr))
#define LDSM4T(r0, r1, r2, r3, addr) \
    asm volatile("ldmatrix.sync.aligned.m8n8.x4.trans.shared.b16 {%0,%1,%2,%3}, [%4];" \
        : "=r"(r0), "=r"(r1), "=r"(r2), "=r"(r3) : "r"(addr))

#define MMA16816(d, a, b) \
    asm volatile("mma.sync.aligned.m16n8k16.row.col.f32.f16.f16.f32 " \
        "{%0,%1,%2,%3}, {%4,%5,%6,%7}, {%8,%9}, {%0,%1,%2,%3};" \
        : "+f"((d)[0]), "+f"((d)[1]), "+f"((d)[2]), "+f"((d)[3]) \
        : "r"((a)[0]), "r"((a)[1]), "r"((a)[2]), "r"((a)[3]), \
          "r"((b)[0]), "r"((b)[1]))

// ---------------------------------------------------------------------------
// convert fp32 -> fp16 (straight, coalesced)
// ---------------------------------------------------------------------------
__global__ __launch_bounds__(256) void conv_f16(
    const float* __restrict__ x, __half* __restrict__ hi, int n4)
{
    int i = blockIdx.x * blockDim.x + threadIdx.x;
    if (i >= n4) return;
    float4 v = ((const float4*)x)[i];
    __half h[4] = {__float2half(v.x), __float2half(v.y),
                   __float2half(v.z), __float2half(v.w)};
    ((uint2*)hi)[i] = *(uint2*)h;
}

// ---------------------------------------------------------------------------
// transpose W[K,N] -> WT[N,K] fp16
// ---------------------------------------------------------------------------
__global__ __launch_bounds__(256) void transpose_half(
    const float* __restrict__ W, __half* __restrict__ T, int K, int N)
{
    __shared__ float t[32][33];
    const int tx = threadIdx.x, ty = threadIdx.y;
    const int n0 = blockIdx.x * 32, k0 = blockIdx.y * 32;
#pragma unroll
    for (int j = 0; j < 32; j += 8)
        t[ty + j][tx] = W[(size_t)(k0 + ty + j) * N + n0 + tx];
    __syncthreads();
#pragma unroll
    for (int j = 0; j < 32; j += 8)
        T[(size_t)(n0 + ty + j) * K + k0 + tx] = __float2half(t[tx][ty + j]);
}

// ---------------------------------------------------------------------------
// Shared GEMM mainloop (proven R10/R12): A[M,K], B^T[N,K] K-major fp16.
// CTA 128x128, KB=32, 3-stage cp.async.
// ---------------------------------------------------------------------------
#define STAGE_BYTES 16384
#define OFF_A 0
#define OFF_B 8192
#define GEMM_SMEM (3 * STAGE_BYTES)     // 49152

__device__ __forceinline__ void load_stage(
    uint32_t sbase, int stage,
    const __half* __restrict__ A, const __half* __restrict__ Bm,
    int m0, int n0, int k0, int K, int tid)
{
    uint32_t base = sbase + stage * STAGE_BYTES;
#pragma unroll
    for (int h = 0; h < 2; h++) {
        int q = tid + h * 256;
        int r = q >> 2, c = q & 3;
        uint32_t so = SWZ(r, c);
        size_t ga = (size_t)(m0 + r) * K + k0 + c * 8;
        size_t gb = (size_t)(n0 + r) * K + k0 + c * 8;
        CP_ASYNC16(base + OFF_A + so, A + ga);
        CP_ASYNC16(base + OFF_B + so, Bm + gb);
    }
}

__device__ __forceinline__ void gemm_mainloop(
    uint32_t sb, float acc[2][8][4],
    const __half* __restrict__ A, const __half* __restrict__ Bm,
    int m0, int n0, int K, int tid, int wid, int l)
{
    const int wm = (wid & 3) * 32, wn = (wid >> 2) * 64;
    const int niter = K / 32;
    load_stage(sb, 0, A, Bm, m0, n0, 0, K, tid);
    CP_COMMIT();
    load_stage(sb, 1, A, Bm, m0, n0, 32, K, tid);
    CP_COMMIT();

    int stage = 0;
    for (int j = 0; j < niter; j++) {
        CP_WAIT1();
        __syncthreads();
        if (j + 2 < niter) {
            int s2 = stage + 2; if (s2 >= 3) s2 -= 3;
            load_stage(sb, s2, A, Bm, m0, n0, (j + 2) * 32, K, tid);
        }
        CP_COMMIT();

        const uint32_t base = sb + stage * STAGE_BYTES;
        const uint32_t abase = base + OFF_A;
        const uint32_t bbase = base + OFF_B;

#pragma unroll
        for (int kk = 0; kk < 2; kk++) {
            uint32_t a_f[2][4];
#pragma unroll
            for (int mi = 0; mi < 2; mi++) {
                int row = wm + mi * 16 + (l & 15);
                int c = kk * 2 + (l >> 4);
                LDSM4(a_f[mi][0], a_f[mi][1], a_f[mi][2], a_f[mi][3],
                      abase + SWZ(row, c));
            }
            uint32_t b_f[8][2];
#pragma unroll
            for (int p = 0; p < 4; p++) {
                int row = wn + p * 16 + ((l >> 4) * 8) + (l & 7);
                int c = kk * 2 + ((l >> 3) & 1);
                LDSM4(b_f[p * 2][0], b_f[p * 2][1], b_f[p * 2 + 1][0], b_f[p * 2 + 1][1],
                      bbase + SWZ(row, c));
            }
#pragma unroll
            for (int mi = 0; mi < 2; mi++)
#pragma unroll
                for (int nj = 0; nj < 8; nj++)
                    MMA16816(acc[mi][nj], a_f[mi], b_f[nj]);
        }
        stage++; if (stage >= 3) stage -= 3;
    }
}

// ---------------------------------------------------------------------------
// GEMM2: out = gate @ WtT^T + bias + resid
// ---------------------------------------------------------------------------
__global__ __launch_bounds__(256) void gemm_hmma(
    const __half* __restrict__ A, const __half* __restrict__ Bm,
    const float* __restrict__ bias, const float* __restrict__ resid,
    float* __restrict__ C, int N, int K)
{
    extern __shared__ char sm[];
    const uint32_t sb = smem_u32(sm);
    const int tid = threadIdx.x, wid = tid >> 5, l = tid & 31;
    const int m0 = blockIdx.y * 128, n0 = blockIdx.x * 128;
    const int wm = (wid & 3) * 32, wn = (wid >> 2) * 64;

    float acc[2][8][4] = {};
    gemm_mainloop(sb, acc, A, Bm, m0, n0, K, tid, wid, l);

#pragma unroll
    for (int mi = 0; mi < 2; mi++) {
#pragma unroll
        for (int nj = 0; nj < 8; nj++) {
            int row0 = m0 + wm + mi * 16 + (l >> 2);
            int col  = n0 + wn + nj * 8 + (l & 3) * 2;
            float bx = bias[col], by = bias[col + 1];
            {
                size_t o = (size_t)row0 * N + col;
                float2 v = {acc[mi][nj][0] + bx, acc[mi][nj][1] + by};
                if (resid) { float2 r = *(const float2*)(resid + o); v.x += r.x; v.y += r.y; }
                *(float2*)(C + o) = v;
            }
            {
                size_t o = (size_t)(row0 + 8) * N + col;
                float2 v = {acc[mi][nj][2] + bx, acc[mi][nj][3] + by};
                if (resid) { float2 r = *(const float2*)(resid + o); v.x += r.x; v.y += r.y; }
                *(float2*)(C + o) = v;
            }
        }
    }
}

// ---------------------------------------------------------------------------
// GEMM1 (proj) with fused epilogue (U fp32 / V fp16 / Q,K RoPE+fp16 repack).
// sincosf epilogue — exact R12 champion math.
// ---------------------------------------------------------------------------
__global__ __launch_bounds__(256) void gemm_proj(
    const __half* __restrict__ A, const __half* __restrict__ Bm,
    const float* __restrict__ bias,
    float* __restrict__ Ubuf,
    __half* __restrict__ qh, __half* __restrict__ kh, __half* __restrict__ vh,
    int N, int K)
{
    extern __shared__ char sm[];
    const uint32_t sb = smem_u32(sm);
    const int tid = threadIdx.x, wid = tid >> 5, l = tid & 31;
    const int m0 = blockIdx.y * 128, n0 = blockIdx.x * 128;
    const int wm = (wid & 3) * 32, wn = (wid >> 2) * 64;

    float acc[2][8][4] = {};
    gemm_mainloop(sb, acc, A, Bm, m0, n0, K, tid, wid, l);

    const int region = n0 >> 10;           // whole CTA in one region

    if (region == 0) {
#pragma unroll
        for (int mi = 0; mi < 2; mi++)
#pragma unroll
            for (int nj = 0; nj < 8; nj++) {
                int row0 = m0 + wm + mi * 16 + (l >> 2);
                int col  = n0 + wn + nj * 8 + (l & 3) * 2;
                float bx = bias[col], by = bias[col + 1];
                *(float2*)(Ubuf + (size_t)row0 * 1024 + col) =
                    make_float2(acc[mi][nj][0] + bx, acc[mi][nj][1] + by);
                *(float2*)(Ubuf + (size_t)(row0 + 8) * 1024 + col) =
                    make_float2(acc[mi][nj][2] + bx, acc[mi][nj][3] + by);
            }
    } else if (region == 1) {
#pragma unroll
        for (int mi = 0; mi < 2; mi++)
#pragma unroll
            for (int nj = 0; nj < 8; nj++) {
                int col = n0 + wn + nj * 8 + (l & 3) * 2;
                int hd = col & 1023, h = hd >> 6, d = hd & 63;
                float bx = bias[col], by = bias[col + 1];
#pragma unroll
                for (int half = 0; half < 2; half++) {
                    int r = m0 + wm + mi * 16 + (l >> 2) + half * 8;
                    int b = r >> 11, s = r & 2047;
                    __half hv[2] = {__float2half(acc[mi][nj][half * 2] + bx),
                                    __float2half(acc[mi][nj][half * 2 + 1] + by)};
                    size_t o = ((size_t)(b * 16 + h) * 2048 + s) * 64 + d;
                    *(uint32_t*)(vh + o) = *(uint32_t*)hv;
                }
            }
    } else {
        const bool isQ = (region == 2);
        __half* dst = isQ ? qh : kh;
        const float scale = isQ ? 0.125f : 1.0f;
#pragma unroll
        for (int mi = 0; mi < 2; mi++)
#pragma unroll
            for (int nj = 0; nj < 4; nj++) {
                int colA = n0 + wn + nj * 8 + (l & 3) * 2;   // d < 32
                int colB = colA + 32;
                int hd = colA & 1023, h = hd >> 6, d = hd & 63;
                float inv0 = __powf(10000.f, -(float)d / 32.f);
                float inv1 = __powf(10000.f, -(float)(d + 1) / 32.f);
                float b1a = bias[colA], b1b = bias[colA + 1];
                float b2a = bias[colB], b2b = bias[colB + 1];
#pragma unroll
                for (int half = 0; half < 2; half++) {
                    int r = m0 + wm + mi * 16 + (l >> 2) + half * 8;
                    int b = r >> 11, s = r & 2047;
                    float sv0, cv0, sv1, cv1;
                    sincosf((float)s * inv0, &sv0, &cv0);
                    sincosf((float)s * inv1, &sv1, &cv1);
                    float x1a = acc[mi][nj][half * 2]     + b1a;
                    float x1b = acc[mi][nj][half * 2 + 1] + b1b;
                    float x2a = acc[mi][nj + 4][half * 2]     + b2a;
                    float x2b = acc[mi][nj + 4][half * 2 + 1] + b2b;
                    __half lo[2] = {__float2half((x1a * cv0 - x2a * sv0) * scale),
                                    __float2half((x1b * cv1 - x2b * sv1) * scale)};
                    __half hi2[2] = {__float2half((x2a * cv0 + x1a * sv0) * scale),
                                     __float2half((x2b * cv1 + x1b * sv1) * scale)};
                    size_t o = ((size_t)(b * 16 + h) * 2048 + s) * 64 + d;
                    *(uint32_t*)(dst + o)      = *(uint32_t*)lo;
                    *(uint32_t*)(dst + o + 32) = *(uint32_t*)hi2;
                }
            }
    }
}

// ---------------------------------------------------------------------------
// HMMA sigmoid attention, fp16, 128-row Q tile, double-buffered K/V.
// 8 warps (4q x 2kv). Pitch 144 B rows. smem 73728 -> 3 CTAs/SM.
// ---------------------------------------------------------------------------
#define OQ2 0
#define OKV0 18432
#define KVSTR 18432            // per-stage: K 9216 + V 9216
#define OP2 55296
#define ATTN_SMEM (73728)

__device__ __forceinline__ void attn_load_kv(
    uint32_t sb, int st, const __half* __restrict__ kh,
    const __half* __restrict__ vh, size_t hbase, int k0, int tid)
{
    uint32_t base = sb + OKV0 + st * KVSTR;
#pragma unroll
    for (int it = 0; it < 2; it++) {
        int i = tid + it * 256;
        int r = i >> 3, c = i & 7;
        uint32_t so = (uint32_t)(r * 144 + c * 16);
        size_t g = hbase + (size_t)(k0 + r) * 64 + c * 8;
        CP_ASYNC16(base + so, kh + g);
        CP_ASYNC16(base + 9216 + so, vh + g);
    }
}

__global__ __launch_bounds__(256) void attn_hmma(
    const __half* __restrict__ qh, const __half* __restrict__ kh,
    const __half* __restrict__ vh, float* __restrict__ out)
{
    extern __shared__ char sm[];
    const uint32_t sb = smem_u32(sm);
    const int tid = threadIdx.x, wid = tid >> 5, l = tid & 31;
    const int bh = blockIdx.x;
    const int qbi = (int)gridDim.y - 1 - (int)blockIdx.y;   // big blocks first
    const int q0 = qbi * 128;
    const size_t hbase = (size_t)bh << 17;                  // bh * 2048 * 64
    const int wq = wid & 3, wn = wid >> 2;

    // ---- load Q tile (128 x 64 fp16) ----
#pragma unroll
    for (int it = 0; it < 4; it++) {
        int i = tid + it * 256;
        int r = i >> 3, c = i & 7;
        uint32_t so = (uint32_t)(r * 144 + c * 16);
        size_t g = hbase + (size_t)(q0 + r) * 64 + c * 8;
        CP_ASYNC16(sb + OQ2 + so, qh + g);
    }
    CP_COMMIT();
    // ---- prologue KV load, stage 0 ----
    attn_load_kv(sb, 0, kh, vh, hbase, 0, tid);
    CP_COMMIT();

    float accO[2][4][4] = {};
    const int nkb = 2 * qbi + 2;

    for (int kb = 0; kb < nkb; kb++) {
        const int k0 = kb * 64;
        // prefetch next KV into alternate buffer (safe: that buffer's last
        // consumer finished before the closing __syncthreads of iter kb-1)
        if (kb + 1 < nkb)
            attn_load_kv(sb, (kb + 1) & 1, kh, vh, hbase, (kb + 1) * 64, tid);
        CP_COMMIT();
        CP_WAIT1();            // Q + KV[0..kb] complete
        __syncthreads();

        const uint32_t kbase = sb + OKV0 + (kb & 1) * KVSTR;
        const uint32_t vbase = kbase + 9216;

        // ---- scores: Q @ K^T ----
        float sc[2][4][4] = {};
#pragma unroll
        for (int ks = 0; ks < 4; ks++) {
            uint32_t aQ[2][4];
#pragma unroll
            for (int mi = 0; mi < 2; mi++) {
                uint32_t ro = (uint32_t)((wq * 32 + mi * 16 + (l & 15)) * 144 +
                                         (ks * 2 + (l >> 4)) * 16);
                LDSM4(aQ[mi][0], aQ[mi][1], aQ[mi][2], aQ[mi][3], sb + OQ2 + ro);
            }
            uint32_t bK[4][2];
#pragma unroll
            for (int g2 = 0; g2 < 2; g2++) {
                int row = wn * 32 + g2 * 16 + ((l >> 4) * 8) + (l & 7);
                uint32_t ro = (uint32_t)(row * 144 + (ks * 2 + ((l >> 3) & 1)) * 16);
                LDSM4(bK[g2 * 2][0], bK[g2 * 2][1], bK[g2 * 2 + 1][0], bK[g2 * 2 + 1][1],
                      kbase + ro);
            }
#pragma unroll
            for (int mi = 0; mi < 2; mi++)
#pragma unroll
                for (int nt = 0; nt < 4; nt++) MMA16816(sc[mi][nt], aQ[mi], bK[nt]);
        }

        // ---- sigmoid + causal mask + fp16 P to smem ----
        const bool edge = (kb >= 2 * qbi);
#pragma unroll
        for (int mi = 0; mi < 2; mi++) {
#pragma unroll
            for (int nt = 0; nt < 4; nt++) {
#pragma unroll
                for (int half = 0; half < 2; half++) {
                    int lq = wq * 32 + mi * 16 + (l >> 2) + half * 8;
                    int lk = wn * 32 + nt * 8 + (l & 3) * 2;
                    float p0 = __fdividef(1.f, 1.f + __expf(-sc[mi][nt][half * 2]));
                    float p1 = __fdividef(1.f, 1.f + __expf(-sc[mi][nt][half * 2 + 1]));
                    if (edge) {
                        if (k0 + lk > q0 + lq) p0 = 0.f;
                        if (k0 + lk + 1 > q0 + lq) p1 = 0.f;
                    }
                    __half hp[2] = {__float2half(p0), __float2half(p1)};
                    *(uint32_t*)(sm + OP2 + (uint32_t)(lq * 144 + lk * 2)) = *(uint32_t*)hp;
                }
            }
        }
        __syncthreads();

        // ---- O += P @ V ----
#pragma unroll
        for (int ks = 0; ks < 4; ks++) {
            uint32_t aP[2][4];
#pragma unroll
            for (int mi = 0; mi < 2; mi++) {
                uint32_t ro = (uint32_t)((wq * 32 + mi * 16 + (l & 15)) * 144 +
                                         (ks * 2 + (l >> 4)) * 16);
                LDSM4(aP[mi][0], aP[mi][1], aP[mi][2], aP[mi][3], sb + OP2 + ro);
            }
            uint32_t bV[4][2];
#pragma unroll
            for (int g2 = 0; g2 < 2; g2++) {
                int row = ks * 16 + (l & 7) + ((l >> 3) & 1) * 8;
                uint32_t ro = (uint32_t)(row * 144 + wn * 64 + g2 * 32 + (l >> 4) * 16);
                LDSM4T(bV[g2 * 2][0], bV[g2 * 2][1], bV[g2 * 2 + 1][0], bV[g2 * 2 + 1][1],
                       vbase + ro);
            }
#pragma unroll
            for (int mi = 0; mi < 2; mi++)
#pragma unroll
                for (int dt = 0; dt < 4; dt++) MMA16816(accO[mi][dt], aP[mi], bV[dt]);
        }
        __syncthreads();
    }

    // ---- epilogue ----
    const int b = bh >> 4, h = bh & 15;
#pragma unroll
    for (int mi = 0; mi < 2; mi++) {
#pragma unroll
        for (int dt = 0; dt < 4; dt++) {
#pragma unroll
            for (int half = 0; half < 2; half++) {
                int q = q0 + wq * 32 + mi * 16 + (l >> 2) + half * 8;
                int d = wn * 32 + dt * 8 + (l & 3) * 2;
                size_t o = ((size_t)(b * 2048 + q)) * 1024 + h * 64 + d;
                float2 v = {accO[mi][dt][half * 2], accO[mi][dt][half * 2 + 1]};
                *(float2*)(out + o) = v;
            }
        }
    }
}

// ---------------------------------------------------------------------------
// Fused LayerNorm + SiLU(U) gate -> fp16  (U already has bias applied)
// ---------------------------------------------------------------------------
__global__ __launch_bounds__(256) void ln_gate_kernel(
    const float* __restrict__ attn, const float* __restrict__ Ubuf,
    const float* __restrict__ g, const float* __restrict__ bb,
    __half* __restrict__ gh)
{
    const int row = blockIdx.x;
    const int tid = threadIdx.x;
    const float* a = attn + (size_t)row * H_;

    float s = 0.f, s2 = 0.f;
    for (int i = tid; i < H_; i += 256) {
        float v = a[i];
        s += v;
        s2 = fmaf(v, v, s2);
    }
    __shared__ float red[2][8];
#pragma unroll
    for (int o = 16; o; o >>= 1) {
        s  += __shfl_xor_sync(~0u, s,  o);
        s2 += __shfl_xor_sync(~0u, s2, o);
    }
    if ((tid & 31) == 0) { red[0][tid >> 5] = s; red[1][tid >> 5] = s2; }
    __syncthreads();
    if (tid < 32) {
        s  = (tid < 8) ? red[0][tid] : 0.f;
        s2 = (tid < 8) ? red[1][tid] : 0.f;
#pragma unroll
        for (int o = 4; o; o >>= 1) {
            s  += __shfl_xor_sync(~0u, s,  o);
            s2 += __shfl_xor_sync(~0u, s2, o);
        }
        if (tid == 0) { red[0][0] = s; red[1][0] = s2; }
    }
    __syncthreads();
    const float mu  = red[0][0] * (1.f / H_);
    const float var = red[1][0] * (1.f / H_) - mu * mu;
    const float rstd = rsqrtf(var + 1e-8f);

    const float* up = Ubuf + (size_t)row * H_;
    for (int i = tid; i < H_; i += 256) {
        float u = up[i];
        float silu = u * __fdividef(1.f, 1.f + __expf(-u));
        float v = silu * ((a[i] - mu) * rstd * g[i] + bb[i]);
        gh[(size_t)row * H_ + i] = __float2half(v);
    }
}

// ---------------------------------------------------------------------------
extern "C" void kernel_launch(void* const* d_in, const int* in_sizes, int n_in,
                              void* d_out, int out_size)
{
    const float* x   = (const float*)d_in[0];
    const float* Wp  = (const float*)d_in[2];
    const float* bp  = (const float*)d_in[3];
    const float* lng = (const float*)d_in[4];
    const float* lnb = (const float*)d_in[5];
    const float* Wt  = (const float*)d_in[6];
    const float* bt  = (const float*)d_in[7];
    float* out = (float*)d_out;

    float *Ubuf, *attn;
    __half *xh, *gh, *WpT, *WtT, *aqh, *akh, *avh;
    cudaGetSymbolAddress((void**)&Ubuf, g_U);
    cudaGetSymbolAddress((void**)&attn, g_attn);
    cudaGetSymbolAddress((void**)&xh, g_xh);
    cudaGetSymbolAddress((void**)&gh, g_gh);
    cudaGetSymbolAddress((void**)&WpT, g_WpT);
    cudaGetSymbolAddress((void**)&WtT, g_WtT);
    cudaGetSymbolAddress((void**)&aqh, g_qh);
    cudaGetSymbolAddress((void**)&akh, g_kh);
    cudaGetSymbolAddress((void**)&avh, g_vh);

    cudaFuncSetAttribute(gemm_hmma,
                         cudaFuncAttributeMaxDynamicSharedMemorySize, GEMM_SMEM);
    cudaFuncSetAttribute(gemm_proj,
                         cudaFuncAttributeMaxDynamicSharedMemorySize, GEMM_SMEM);
    cudaFuncSetAttribute(attn_hmma,
                         cudaFuncAttributeMaxDynamicSharedMemorySize, ATTN_SMEM);

    // 0) convert + weight transposes
    conv_f16<<<(M_ * H_ / 4 + 255) / 256, 256>>>(x, xh, M_ * H_ / 4);
    transpose_half<<<dim3(4 * H_ / 32, H_ / 32), dim3(32, 8)>>>(Wp, WpT, H_, 4 * H_);
    transpose_half<<<dim3(H_ / 32, H_ / 32), dim3(32, 8)>>>(Wt, WtT, H_, H_);

    // 1) proj GEMM with fused bias + RoPE + fp16 repack epilogue
    gemm_proj<<<dim3(4 * H_ / 128, M_ / 128), 256, GEMM_SMEM>>>(
        xh, WpT, bp, Ubuf, aqh, akh, avh, 4 * H_, H_);

    // 2) HMMA sigmoid attention (double-buffered K/V) -> attn [8192, 1024]
    attn_hmma<<<dim3(B_ * NH, S_ / 128), 256, ATTN_SMEM>>>(aqh, akh, avh, attn);

    // 3) LN + SiLU gate -> fp16
    ln_gate_kernel<<<M_, 256>>>(attn, Ubuf, lng, lnb, gh);

    // 4) out = x + gate @ Wt + bt
    gemm_hmma<<<dim3(H_ / 128, M_ / 128), 256, GEMM_SMEM>>>(
        gh, WtT, bt, x, out, H_, H_);
}